// round 1
// baseline (speedup 1.0000x reference)
#include <cuda_runtime.h>
#include <math.h>

// Problem constants (fixed shapes from reference setup_inputs)
#define IMG_H 512
#define IMG_W 960
#define NCH 3

#define TW 32
#define TH 16

#define ALPHA 0.85f
#define C1 (0.01f * 0.01f)
#define C2 (0.03f * 0.03f)
#define EPS2 (0.001f * 0.001f)

// global accumulators: [0]=photo_num, [1]=lr_num, [2]=den (== lr_den == sum(valid))
__device__ double g_acc[3];

__global__ void init_acc_kernel() {
    if (threadIdx.x < 3) g_acc[threadIdx.x] = 0.0;
}

__global__ __launch_bounds__(256) void stereo_loss_kernel(
    const float* __restrict__ left,
    const float* __restrict__ right,
    const float* __restrict__ d_left,
    const float* __restrict__ d_right,
    const float* __restrict__ nonocc)
{
    const int W = IMG_W, H = IMG_H;
    __shared__ float sL[NCH][TH + 2][TW + 2];
    __shared__ float sY[NCH][TH + 2][TW + 2];
    __shared__ float sD[TH + 2][TW + 2];

    const int w0 = blockIdx.x * TW;
    const int h0 = blockIdx.y * TH;
    const int b  = blockIdx.z;

    const size_t planeHW = (size_t)H * W;
    const float* Lb  = left    + (size_t)b * NCH * planeHW;
    const float* Rb  = right   + (size_t)b * NCH * planeHW;
    const float* Db  = d_left  + (size_t)b * planeHW;
    const float* DRb = d_right + (size_t)b * planeHW;
    const float* Nb  = nonocc  + (size_t)b * planeHW;

    // ---- halo fill: left, d_left, warped right for (TH+2)x(TW+2) region ----
    for (int idx = threadIdx.x; idx < (TH + 2) * (TW + 2); idx += 256) {
        int i = idx / (TW + 2);
        int j = idx % (TW + 2);
        int gh = h0 - 1 + i;
        int gw = w0 - 1 + j;
        if (gh >= 0 && gh < H && gw >= 0 && gw < W) {
            float d = Db[(size_t)gh * W + gw];
            sD[i][j] = d;
            float x  = (float)gw - d;
            float x0 = floorf(x);
            float wx = x - x0;
            int   xi = (int)x0;
            int x0i = min(max(xi, 0), W - 1);
            int x1i = min(max(xi + 1, 0), W - 1);
            const float* rrow = Rb + (size_t)gh * W;
            const float* lrow = Lb + (size_t)gh * W;
            #pragma unroll
            for (int c = 0; c < NCH; c++) {
                float v0 = rrow[(size_t)c * planeHW + x0i];
                float v1 = rrow[(size_t)c * planeHW + x1i];
                sY[c][i][j] = (1.0f - wx) * v0 + wx * v1;
                sL[c][i][j] = lrow[(size_t)c * planeHW + gw];
            }
        }
    }
    __syncthreads();

    const bool interior = (h0 >= 1) && (h0 + TH <= H - 1) &&
                          (w0 >= 1) && (w0 + TW <= W - 1);

    const int tx  = threadIdx.x & 31;
    const int tyb = threadIdx.x >> 5;

    float accP = 0.0f, accL = 0.0f, accD = 0.0f;

    #pragma unroll
    for (int rr = 0; rr < 2; rr++) {
        const int r  = tyb + rr * 8;          // 0..15
        const int gh = h0 + r;
        const int gw = w0 + tx;
        // exact tiling: gh<H, gw<W always

        // validity / weight first (skip heavy work when weight is zero)
        float dl = sD[r + 1][tx + 1];
        float x  = (float)gw - dl;
        float gx = 2.0f * x / (float)(W - 1) - 1.0f;
        float vb = (gx >= -1.0f && gx <= 1.0f) ? 1.0f : 0.0f;
        float wv = vb * Nb[(size_t)gh * W + gw];
        accD += wv;

        if (wv != 0.0f) {
            float n;
            if (interior) {
                n = 9.0f;
            } else {
                float rows = 1.0f + (gh > 0 ? 1.0f : 0.0f) + (gh < H - 1 ? 1.0f : 0.0f);
                float cols = 1.0f + (gw > 0 ? 1.0f : 0.0f) + (gw < W - 1 ? 1.0f : 0.0f);
                n = rows * cols;
            }
            float inv = 1.0f / n;

            float ssum = 0.0f, l1sum = 0.0f;
            #pragma unroll
            for (int c = 0; c < NCH; c++) {
                float sx = 0.f, sy = 0.f, sxx = 0.f, syy = 0.f, sxy = 0.f;
                if (interior) {
                    #pragma unroll
                    for (int dy = 0; dy < 3; dy++) {
                        #pragma unroll
                        for (int dx = 0; dx < 3; dx++) {
                            float a  = sL[c][r + dy][tx + dx];
                            float bv = sY[c][r + dy][tx + dx];
                            sx  += a;
                            sy  += bv;
                            sxx += a * a;
                            syy += bv * bv;
                            sxy += a * bv;
                        }
                    }
                } else {
                    for (int dy = 0; dy < 3; dy++) {
                        int hh = gh - 1 + dy;
                        if (hh < 0 || hh >= H) continue;
                        for (int dx = 0; dx < 3; dx++) {
                            int ww = gw - 1 + dx;
                            if (ww < 0 || ww >= W) continue;
                            float a  = sL[c][r + dy][tx + dx];
                            float bv = sY[c][r + dy][tx + dx];
                            sx  += a;
                            sy  += bv;
                            sxx += a * a;
                            syy += bv * bv;
                            sxy += a * bv;
                        }
                    }
                }
                float mux   = sx * inv;
                float muy   = sy * inv;
                float sigx  = sxx * inv - mux * mux;
                float sigy  = syy * inv - muy * muy;
                float sigxy = sxy * inv - mux * muy;
                float num = (2.0f * mux * muy + C1) * (2.0f * sigxy + C2);
                float den = (mux * mux + muy * muy + C1) * (sigx + sigy + C2);
                float ssim = num / (den + 1e-12f);
                ssum += fminf(fmaxf((1.0f - ssim) * 0.5f, 0.0f), 1.0f);

                float d0 = sL[c][r + 1][tx + 1] - sY[c][r + 1][tx + 1];
                l1sum += sqrtf(d0 * d0 + EPS2);
            }
            float photo = ALPHA * (ssum * (1.0f / 3.0f)) +
                          (1.0f - ALPHA) * (l1sum * (1.0f / 3.0f));
            accP += photo * wv;

            // warp d_right with the same d_left (valid_r == valid)
            float x0f = floorf(x);
            float wx  = x - x0f;
            int   xi  = (int)x0f;
            int x0i = min(max(xi, 0), W - 1);
            int x1i = min(max(xi + 1, 0), W - 1);
            const float* drow = DRb + (size_t)gh * W;
            float drw = (1.0f - wx) * drow[x0i] + wx * drow[x1i];
            float dd = dl - drw;
            accL += sqrtf(dd * dd + EPS2) * wv;
        }
    }

    // ---- block reduction ----
    #pragma unroll
    for (int o = 16; o > 0; o >>= 1) {
        accP += __shfl_down_sync(0xFFFFFFFFu, accP, o);
        accL += __shfl_down_sync(0xFFFFFFFFu, accL, o);
        accD += __shfl_down_sync(0xFFFFFFFFu, accD, o);
    }
    __shared__ float red[3][8];
    int lane = threadIdx.x & 31;
    int wid  = threadIdx.x >> 5;
    if (lane == 0) {
        red[0][wid] = accP;
        red[1][wid] = accL;
        red[2][wid] = accD;
    }
    __syncthreads();
    if (threadIdx.x == 0) {
        double p = 0.0, l = 0.0, d = 0.0;
        #pragma unroll
        for (int i = 0; i < 8; i++) {
            p += (double)red[0][i];
            l += (double)red[1][i];
            d += (double)red[2][i];
        }
        atomicAdd(&g_acc[0], p);
        atomicAdd(&g_acc[1], l);
        atomicAdd(&g_acc[2], d);
    }
}

__global__ void finalize_kernel(float* __restrict__ out, int total_px) {
    if (threadIdx.x == 0) {
        double den   = g_acc[2];
        double photo = g_acc[0] / (den + 1e-6);
        double lr    = g_acc[1] / (den + 1e-6);
        out[0] = (float)(photo + 0.2 * lr);   // total (W_PHOTO=1, W_LR=0.2)
        out[1] = (float)photo;                // photo_loss
        out[2] = (float)lr;                   // lr_loss
        out[3] = (float)(den / (double)total_px); // valid_ratio
    }
}

extern "C" void kernel_launch(void* const* d_in, const int* in_sizes, int n_in,
                              void* d_out, int out_size) {
    const float* left    = (const float*)d_in[0];
    const float* right   = (const float*)d_in[1];
    const float* d_left  = (const float*)d_in[2];
    const float* d_right = (const float*)d_in[3];
    const float* nonocc  = (const float*)d_in[4];
    float* out = (float*)d_out;

    // B derived from d_left element count (shape [B,1,H,W])
    int B = in_sizes[2] / (IMG_H * IMG_W);

    init_acc_kernel<<<1, 32>>>();

    dim3 grid(IMG_W / TW, IMG_H / TH, B);
    stereo_loss_kernel<<<grid, 256>>>(left, right, d_left, d_right, nonocc);

    finalize_kernel<<<1, 32>>>(out, B * IMG_H * IMG_W);
}